// round 10
// baseline (speedup 1.0000x reference)
#include <cuda_runtime.h>
#include <cuda_bf16.h>
#include <cstdint>

// HilbertSchmidtVQ forward: out == rho_flat bitwise, since
// quantized - stop_gradient(quantized) == 0 exactly (value-identity).
// The forward pass is a pure 64 MB device-to-device copy.
//
// R10: SM-originated copies (LDG/STG in every width/policy/occupancy config,
// R2-R9) are pinned at the chip LTS cap: 128 MB of L2 traffic / ~6300 B/cyc
// = 18.3 us kernel, invariant across 9 rounds. The only remaining engine is
// the COPY ENGINE: a cudaMemcpyAsync D2D captured as a graph memcpy node
// (explicitly permitted by the harness). CE DMA is a different L2 requestor
// and is not covered by the SM-side LTS-cap measurements; it also removes
// kernel launch/drain overhead from each replay.
// If CE is subject to the same cap, this is flat (~18.5-19 us) and the floor
// is proven engine-independent; if not, 12-16 us.

extern "C" void kernel_launch(void* const* d_in, const int* in_sizes, int n_in,
                              void* d_out, int out_size) {
    // in[0] = rho_flat (N*DIM = 16,777,216 floats = 64 MiB); out is same size.
    const size_t bytes = (size_t)out_size * sizeof(float);
    cudaMemcpyAsync(d_out, d_in[0], bytes, cudaMemcpyDeviceToDevice, 0);
}

// round 11
// speedup vs baseline: 1.3088x; 1.3088x over previous
#include <cuda_runtime.h>
#include <cuda_bf16.h>
#include <cstdint>

// HilbertSchmidtVQ forward: out == rho_flat bitwise, since
// quantized - stop_gradient(quantized) == 0 exactly (same array subtracted
// from itself; stop_gradient is a value-identity). The distance matrix,
// argmin, and gather affect gradients only. The forward pass is therefore a
// pure 64 MB device-to-device copy.
//
// FINAL — measured hardware roofline. The copy is bound by the B300
// chip-level LTS throughput cap (~6300 B/cyc): LTS traffic is irreducibly
// 128 MB (64 MB load + 64 MB store requests), a hard floor of ~18.3 us.
// Evidence across 10 rounds:
//   - occupancy 50->80%, MLP 1->8, LDG.128 vs LDG.256: flat at 18.2-18.6 us
//   - L2 residency input/output/split + all cache policies: flat or worse
//   - copy-engine memcpy graph node: 25.1 us (slower) -> floor is
//     engine-independent
// This configuration (regs=32, occ ~80%) sits exactly on the cap at
// ~7.0 TB/s of L2 throughput.
//
//  - 8x front-batched independent LDG.128 per thread (MLP=8)
//  - no bounds predicates: 4,194,304 float4 = 2048 CTAs x 256 thr x 8 exact
//  - st.global.cs evict-first stores: write stream leaves L2 quickly so the
//    input stays L2-resident across graph replays (DRAM traffic ~= writes
//    only), minimizing DRAM pressure under the LTS cap.

#define UNROLL 8
#define THREADS 256

__global__ __launch_bounds__(THREADS) void vq_forward_copy_kernel(
    const float4* __restrict__ src, float4* __restrict__ dst)
{
    const size_t base = (size_t)blockIdx.x * (THREADS * UNROLL) + threadIdx.x;
    const float4* s = src + base;
    float4*       d = dst + base;

    float4 v[UNROLL];

    // Front-batched independent 128-bit loads (MLP=8).
#pragma unroll
    for (int k = 0; k < UNROLL; ++k) {
        v[k] = s[k * THREADS];
    }

    // Evict-first stores: write stream leaves L2 quickly, input stays resident.
#pragma unroll
    for (int k = 0; k < UNROLL; ++k) {
        asm volatile("st.global.cs.v4.f32 [%0], {%1, %2, %3, %4};"
                     :: "l"(d + k * THREADS),
                        "f"(v[k].x), "f"(v[k].y), "f"(v[k].z), "f"(v[k].w)
                     : "memory");
    }
}

extern "C" void kernel_launch(void* const* d_in, const int* in_sizes, int n_in,
                              void* d_out, int out_size) {
    const float4* src = (const float4*)d_in[0];
    float4* dst = (float4*)d_out;

    const int n_vec = out_size / 4;           // 4,194,304 float4
    const int per_cta = THREADS * UNROLL;     // 2048 float4 per CTA
    const int blocks = n_vec / per_cta;       // exactly 2048 CTAs
    vq_forward_copy_kernel<<<blocks, THREADS>>>(src, dst);
}